// round 16
// baseline (speedup 1.0000x reference)
#include <cuda_runtime.h>
#include <cuda_fp16.h>
#include <cstdint>

#define TS   2048
#define HD   1024
#define FFD  1024
#define NE   16
#define NK   4
#define NCH  16                        // K chunks of 64 halfs
#define ARB  144                       // A smem row bytes (64 halfs + pad)
#define BRB  528                       // B smem row bytes (256 halfs + pad)
#define ATILE (128 * ARB)              // 18432
#define BTILE (64 * BRB)               // 33792
#define STAGE (ATILE + BTILE)          // 52224
#define DSMEM (3 * STAGE)              // 156672
#define RTOK 8                         // tokens per router block

// ---------------- scratch (device globals) ----------------
struct Ctr { int counts[NE]; float imp[NE]; int loadcnt[NK]; };
__device__ Ctr    g_ctr;
__device__ int    g_tok[NE][TS];
__device__ float  g_gate[NE][TS];
__device__ __half g_xh[(size_t)TS * HD];               // x fp16
__device__ __half g_win_h[(size_t)NE * HD * 2 * FFD];  // W_in fp16, original [e][k][n]
__device__ __half g_wout_h[(size_t)NE * FFD * HD];     // W_out fp16, original [e][k][n]
__device__ __half g_act_h[(size_t)NE * TS * FFD];      // activations fp16

// ---------------- helpers ----------------
__device__ __forceinline__ void mma_f16(float d[4], const uint32_t a[4], const uint32_t b[2]) {
    asm volatile(
        "mma.sync.aligned.m16n8k16.row.col.f32.f16.f16.f32 "
        "{%0,%1,%2,%3}, {%4,%5,%6,%7}, {%8,%9}, {%0,%1,%2,%3};"
        : "+f"(d[0]), "+f"(d[1]), "+f"(d[2]), "+f"(d[3])
        : "r"(a[0]), "r"(a[1]), "r"(a[2]), "r"(a[3]), "r"(b[0]), "r"(b[1]));
}
__device__ __forceinline__ void ldsm4(uint32_t r[4], uint32_t addr) {
    asm volatile("ldmatrix.sync.aligned.m8n8.x4.shared.b16 {%0,%1,%2,%3}, [%4];"
        : "=r"(r[0]), "=r"(r[1]), "=r"(r[2]), "=r"(r[3]) : "r"(addr));
}
__device__ __forceinline__ void ldsm4t(uint32_t r[4], uint32_t addr) {
    asm volatile("ldmatrix.sync.aligned.m8n8.x4.trans.shared.b16 {%0,%1,%2,%3}, [%4];"
        : "=r"(r[0]), "=r"(r[1]), "=r"(r[2]), "=r"(r[3]) : "r"(addr));
}
__device__ __forceinline__ uint32_t s2u(const void* p) {
    return (uint32_t)__cvta_generic_to_shared(p);
}
__device__ __forceinline__ void cpa16(uint32_t dst, const void* src) {
    asm volatile("cp.async.ca.shared.global [%0], [%1], 16;" :: "r"(dst), "l"(src));
}
__device__ __forceinline__ void cpa_commit() { asm volatile("cp.async.commit_group;"); }
template<int N> __device__ __forceinline__ void cpa_wait() {
    asm volatile("cp.async.wait_group %0;" :: "n"(N));
}
union H4U4 { __half2 h[4]; uint4 u; };

// ---------------- kernel: W_in fp32->fp16 + ctr zero + d_out zero ----------------
__global__ void conv_win_kernel(const float* __restrict__ Win,
                                float* __restrict__ out, int out_size, int wblocks) {
    const int b = blockIdx.x, tid = threadIdx.x;
    if (b == 0 && tid < (int)(sizeof(Ctr) / 4)) {
        ((int*)&g_ctr)[tid] = 0;
    }
    if (b < wblocks) {
        size_t i = ((size_t)b * 256 + tid) * 8;
        float4 a = *(const float4*)(Win + i);
        float4 c = *(const float4*)(Win + i + 4);
        H4U4 pk;
        pk.h[0] = __floats2half2_rn(a.x, a.y);
        pk.h[1] = __floats2half2_rn(a.z, a.w);
        pk.h[2] = __floats2half2_rn(c.x, c.y);
        pk.h[3] = __floats2half2_rn(c.z, c.w);
        *(uint4*)(g_win_h + i) = pk.u;
    } else {
        int i = (b - wblocks) * 2048 + tid * 8;
        if (i + 8 <= out_size) {
            *(float4*)(out + i)     = make_float4(0.f, 0.f, 0.f, 0.f);
            *(float4*)(out + i + 4) = make_float4(0.f, 0.f, 0.f, 0.f);
        } else {
            for (int j = 0; j < 8; j++)
                if (i + j < out_size) out[i + j] = 0.f;
        }
    }
}

// ---------------- kernel: W_out fp32->fp16 (runs on side stream under g1) ----------------
__global__ void conv_wout_kernel(const float* __restrict__ Wout) {
    size_t i = ((size_t)blockIdx.x * 256 + threadIdx.x) * 8;
    float4 a = *(const float4*)(Wout + i);
    float4 c = *(const float4*)(Wout + i + 4);
    H4U4 pk;
    pk.h[0] = __floats2half2_rn(a.x, a.y);
    pk.h[1] = __floats2half2_rn(a.z, a.w);
    pk.h[2] = __floats2half2_rn(c.x, c.y);
    pk.h[3] = __floats2half2_rn(c.z, c.w);
    *(uint4*)(g_wout_h + i) = pk.u;
}

// ---------------- kernel: router, 8 tokens/block, rw in registers ----------------
__global__ void __launch_bounds__(256) router_kernel(const float* __restrict__ x,
                                                     const float* __restrict__ rw,
                                                     const float* __restrict__ rb) {
    __shared__ float xs[RTOK][HD];
    __shared__ float lg[RTOK][NE];
    const int s0 = blockIdx.x * RTOK, tid = threadIdx.x;
    for (int i = tid; i < RTOK * HD / 4; i += 256)
        ((float4*)xs)[i] = ((const float4*)(x + (size_t)s0 * HD))[i];
    __syncthreads();
    for (int i = tid; i < RTOK * HD / 2; i += 256) {
        float2 v = ((const float2*)xs)[i];
        ((__half2*)(g_xh + (size_t)s0 * HD))[i] = __floats2half2_rn(v.x, v.y);
    }
    const int w = tid >> 5, lane = tid & 31;
    #pragma unroll
    for (int ee = 0; ee < 2; ee++) {
        const int e = w * 2 + ee;
        const float* r = rw + (size_t)e * HD;
        float rreg[32];
        #pragma unroll
        for (int j = 0; j < 32; j++) rreg[j] = r[lane + 32 * j];
        #pragma unroll
        for (int t = 0; t < RTOK; t++) {
            float p = 0.f;
            #pragma unroll
            for (int j = 0; j < 32; j++) p += rreg[j] * xs[t][lane + 32 * j];
            #pragma unroll
            for (int o = 16; o; o >>= 1) p += __shfl_xor_sync(0xFFFFFFFFu, p, o);
            if (lane == 0) lg[t][e] = p + rb[e];
        }
    }
    __syncthreads();
    if (tid < RTOK) {
        const int s = s0 + tid;
        float v[NE];
        #pragma unroll
        for (int e = 0; e < NE; e++) v[e] = lg[tid][e];
        int idx[NK]; float tv[NK]; bool used[NE];
        #pragma unroll
        for (int e = 0; e < NE; e++) used[e] = false;
        for (int k = 0; k < NK; k++) {
            int bi = 0; float bv = -3.0e38f;
            for (int e = 0; e < NE; e++)
                if (!used[e] && v[e] > bv) { bv = v[e]; bi = e; }
            used[bi] = true; idx[k] = bi; tv[k] = bv;
        }
        float w4[NK], den = 0.f, m = tv[0];
        for (int k = 0; k < NK; k++) { w4[k] = expf(tv[k] - m); den += w4[k]; }
        for (int k = 0; k < NK; k++) w4[k] /= den;
        float mm = v[0];
        for (int e = 1; e < NE; e++) mm = fmaxf(mm, v[e]);
        float pr[NE], d2 = 0.f;
        for (int e = 0; e < NE; e++) { pr[e] = expf(v[e] - mm); d2 += pr[e]; }
        for (int e = 0; e < NE; e++) atomicAdd(&g_ctr.imp[e], pr[e] / d2);
        int jm = 0;
        for (int k = 1; k < NK; k++) if (idx[k] > idx[jm]) jm = k;
        atomicAdd(&g_ctr.loadcnt[jm], 1);
        for (int k = 0; k < NK; k++) {
            int e = idx[k];
            int slot = atomicAdd(&g_ctr.counts[e], 1);
            g_tok[e][slot]  = s;
            g_gate[e][slot] = w4[k];
        }
    }
}

// ---------------- GEMM1: 128m x 128f, B interleaved (up|gate per 8-col granule) ----------------
__global__ void __launch_bounds__(256, 1) g1_kernel(const float* __restrict__ bin) {
    extern __shared__ __align__(16) char dsm[];
    __shared__ int toks[128];
    __shared__ float bUs[128], bGs[128];
    const int e = blockIdx.z, m0 = blockIdx.x * 128, nf0 = blockIdx.y * 128;
    const int cnt = g_ctr.counts[e];
    if (m0 >= cnt) return;
    const int tid = threadIdx.x;
    if (tid < 128) {
        int r = m0 + tid;
        toks[tid] = (r < cnt) ? g_tok[e][r] : g_tok[e][0];
        bUs[tid] = bin[(size_t)e * 2 * FFD + nf0 + tid];
    } else {
        bGs[tid - 128] = bin[(size_t)e * 2 * FFD + FFD + nf0 + (tid - 128)];
    }
    __syncthreads();

    const uint32_t smu = s2u(dsm);
    const __half* Wb = g_win_h + (size_t)e * HD * (2 * FFD);

    auto load_chunk = [&](int c, int s) {
        const int k0 = c * 64;
        const uint32_t ab = smu + (uint32_t)s * STAGE, bb = ab + ATILE;
        #pragma unroll
        for (int g = 0; g < 4; g++) {
            int gg = g * 256 + tid, r = gg >> 3, cc = gg & 7;
            cpa16(ab + (uint32_t)(r * ARB + cc * 16),
                  g_xh + (size_t)toks[r] * HD + k0 + cc * 8);
        }
        #pragma unroll
        for (int g = 0; g < 8; g++) {
            int gg = g * 256 + tid, r = gg >> 5, g32 = gg & 31;
            int t = g32 >> 1;
            int n = ((g32 & 1) == 0) ? (nf0 + t * 8) : (FFD + nf0 + t * 8);
            cpa16(bb + (uint32_t)(r * BRB + g32 * 16),
                  Wb + (size_t)(k0 + r) * (2 * FFD) + n);
        }
        cpa_commit();
    };

    const int wid = tid >> 5, lane = tid & 31;
    const int wm = wid >> 2, wn = wid & 3;
    const int gq = lane >> 2, tg = lane & 3;
    const int rsel = lane & 7, seg = (lane >> 3) & 1, hsel = lane >> 4;
    const uint32_t aoff = (uint32_t)((rsel + seg * 8) * ARB + hsel * 16);
    const uint32_t boff = (uint32_t)((lane & 15) * BRB + (lane >> 4) * 16);
    float acc[4][8][4] = {};

    load_chunk(0, 0); load_chunk(1, 1);
    #pragma unroll 1
    for (int c = 0; c < NCH; c++) {
        if (c == NCH - 1) cpa_wait<0>(); else cpa_wait<1>();
        __syncthreads();
        if (c + 2 < NCH) load_chunk(c + 2, (c + 2) % 3);
        const uint32_t st = smu + (uint32_t)(c % 3) * STAGE;
        const uint32_t abase = st + (uint32_t)(wm * 64 * ARB) + aoff;
        const uint32_t bbase = st + ATILE + (uint32_t)(wn * 128) + boff;
        #pragma unroll
        for (int k16 = 0; k16 < 4; k16++) {
            uint32_t a[4][4];
            #pragma unroll
            for (int i = 0; i < 4; i++) ldsm4(a[i], abase + i * 16 * ARB + k16 * 32);
            #pragma unroll
            for (int j2 = 0; j2 < 4; j2++) {
                uint32_t b4[4];
                ldsm4t(b4, bbase + k16 * 16 * BRB + j2 * 32);
                #pragma unroll
                for (int i = 0; i < 4; i++) {
                    mma_f16(acc[i][2*j2],     a[i], &b4[0]);
                    mma_f16(acc[i][2*j2 + 1], a[i], &b4[2]);
                }
            }
        }
    }

    // register-resident SwiGLU epilogue, coalesced half2 stores
    const int mlim = cnt - m0;
    float2 bu[4], bg[4];
    #pragma unroll
    for (int p = 0; p < 4; p++) {
        int f0 = wn * 32 + p * 8 + 2 * tg;
        bu[p] = *(float2*)&bUs[f0];
        bg[p] = *(float2*)&bGs[f0];
    }
    #pragma unroll
    for (int i = 0; i < 4; i++) {
        int r0 = wm * 64 + i * 16 + gq;
        #pragma unroll
        for (int h = 0; h < 2; h++) {
            int row = r0 + h * 8;
            if (row < mlim) {
                __half* arow = g_act_h + ((size_t)e * TS + m0 + row) * FFD + nf0;
                #pragma unroll
                for (int p = 0; p < 4; p++) {
                    int f0 = wn * 32 + p * 8 + 2 * tg;
                    float up0 = acc[i][2*p][2*h]     + bu[p].x;
                    float up1 = acc[i][2*p][2*h + 1] + bu[p].y;
                    float gt0 = acc[i][2*p+1][2*h]     + bg[p].x;
                    float gt1 = acc[i][2*p+1][2*h + 1] + bg[p].y;
                    up0 = fminf(fmaxf(up0, -7.f), 7.f);
                    up1 = fminf(fmaxf(up1, -7.f), 7.f);
                    gt0 = fminf(fmaxf(gt0, -7.f), 7.f);
                    gt1 = fminf(fmaxf(gt1, -7.f), 7.f);
                    float o0 = gt0 / (1.f + expf(-gt0)) * up0;
                    float o1 = gt1 / (1.f + expf(-gt1)) * up1;
                    *(__half2*)(arow + f0) = __floats2half2_rn(o0, o1);
                }
            }
        }
    }
}

// ---------------- GEMM2: 128m x 256n, warp 64x64, weighted atomic scatter + aux ----------------
__global__ void __launch_bounds__(256, 1) g2_kernel(const float* __restrict__ bout,
                                                    float* __restrict__ out, int out_size) {
    extern __shared__ __align__(16) char dsm[];
    __shared__ int toks[128];
    __shared__ float gws[128];
    const int e = blockIdx.z, m0 = blockIdx.x * 128, n0 = blockIdx.y * 256;
    const int tid = threadIdx.x;
    if (e == 0 && blockIdx.x == 0 && blockIdx.y == 0 && tid == 0 && out_size > TS * HD) {
        float a = 0.f;
        #pragma unroll
        for (int j = 0; j < NK; j++)
            a += (g_ctr.imp[j] / (float)TS) * ((float)g_ctr.loadcnt[j] / (float)TS);
        out[TS * HD] = 0.02f * (float)NE * a;
    }
    const int cnt = g_ctr.counts[e];
    if (m0 >= cnt) return;
    if (tid < 128) {
        int r = m0 + tid;
        toks[tid] = (r < cnt) ? g_tok[e][r] : 0;
        gws[tid]  = (r < cnt) ? g_gate[e][r] : 0.f;
    }
    __syncthreads();

    const uint32_t smu = s2u(dsm);
    const __half* Wb = g_wout_h + (size_t)e * FFD * HD;
    const __half* Arows = g_act_h + ((size_t)e * TS + m0) * FFD;

    auto load_chunk = [&](int c, int s) {
        const int k0 = c * 64;
        const uint32_t ab = smu + (uint32_t)s * STAGE, bb = ab + ATILE;
        #pragma unroll
        for (int g = 0; g < 4; g++) {
            int gg = g * 256 + tid, r = gg >> 3, cc = gg & 7;
            cpa16(ab + (uint32_t)(r * ARB + cc * 16),
                  Arows + (size_t)r * FFD + k0 + cc * 8);
        }
        #pragma unroll
        for (int g = 0; g < 8; g++) {
            int gg = g * 256 + tid, r = gg >> 5, g32 = gg & 31;
            cpa16(bb + (uint32_t)(r * BRB + g32 * 16),
                  Wb + (size_t)(k0 + r) * HD + n0 + g32 * 8);
        }
        cpa_commit();
    };

    const int wid = tid >> 5, lane = tid & 31;
    const int wm = wid >> 2, wn = wid & 3;
    const int gq = lane >> 2, tg = lane & 3;
    const int rsel = lane & 7, seg = (lane >> 3) & 1, hsel = lane >> 4;
    const uint32_t aoff = (uint32_t)((rsel + seg * 8) * ARB + hsel * 16);
    const uint32_t boff = (uint32_t)((lane & 15) * BRB + (lane >> 4) * 16);
    float acc[4][8][4] = {};

    load_chunk(0, 0); load_chunk(1, 1);
    #pragma unroll 1
    for (int c = 0; c < NCH; c++) {
        if (c == NCH - 1) cpa_wait<0>(); else cpa_wait<1>();
        __syncthreads();
        if (c + 2 < NCH) load_chunk(c + 2, (c + 2) % 3);
        const uint32_t st = smu + (uint32_t)(c % 3) * STAGE;
        const uint32_t abase = st + (uint32_t)(wm * 64 * ARB) + aoff;
        const uint32_t bbase = st + ATILE + (uint32_t)(wn * 128) + boff;
        #pragma unroll
        for (int k16 = 0; k16 < 4; k16++) {
            uint32_t a[4][4];
            #pragma unroll
            for (int i = 0; i < 4; i++) ldsm4(a[i], abase + i * 16 * ARB + k16 * 32);
            #pragma unroll
            for (int j2 = 0; j2 < 4; j2++) {
                uint32_t b4[4];
                ldsm4t(b4, bbase + k16 * 16 * BRB + j2 * 32);
                #pragma unroll
                for (int i = 0; i < 4; i++) {
                    mma_f16(acc[i][2*j2],     a[i], &b4[0]);
                    mma_f16(acc[i][2*j2 + 1], a[i], &b4[2]);
                }
            }
        }
    }

    const float* bo = bout + (size_t)e * HD + n0;
    #pragma unroll
    for (int i = 0; i < 4; i++) {
        int r0 = wm * 64 + i * 16 + gq;
        #pragma unroll
        for (int h = 0; h < 2; h++) {
            int row = r0 + h * 8;
            if (m0 + row < cnt) {
                float gw = gws[row];
                float* orow = out + (size_t)toks[row] * HD + n0;
                #pragma unroll
                for (int j = 0; j < 8; j++) {
                    int c0 = wn * 64 + j * 8 + 2 * tg;
                    atomicAdd(&orow[c0],     gw * (acc[i][j][2 * h]     + bo[c0]));
                    atomicAdd(&orow[c0 + 1], gw * (acc[i][j][2 * h + 1] + bo[c0 + 1]));
                }
            }
        }
    }
}

// ---------------- launcher: conv_Wout hidden under g1 via side stream ----------------
extern "C" void kernel_launch(void* const* d_in, const int* in_sizes, int n_in,
                              void* d_out, int out_size) {
    const float* x    = (const float*)d_in[0];
    const float* Win  = (const float*)d_in[1];
    const float* bin  = (const float*)d_in[2];
    const float* Wout = (const float*)d_in[3];
    const float* bout = (const float*)d_in[4];
    const float* rw   = (const float*)d_in[5];
    const float* rb   = (const float*)d_in[6];
    float* out = (float*)d_out;

    cudaFuncSetAttribute(g1_kernel, cudaFuncAttributeMaxDynamicSharedMemorySize, DSMEM);
    cudaFuncSetAttribute(g2_kernel, cudaFuncAttributeMaxDynamicSharedMemorySize, DSMEM);

    cudaStream_t s1;
    cudaStreamCreateWithFlags(&s1, cudaStreamNonBlocking);
    cudaEvent_t e1, e2;
    cudaEventCreateWithFlags(&e1, cudaEventDisableTiming);
    cudaEventCreateWithFlags(&e2, cudaEventDisableTiming);

    const int w1blocks = NE * HD * 2 * FFD / 2048;   // 16384
    const int zblocks  = (out_size + 2047) / 2048;   // ~1025
    const int w2blocks = NE * FFD * HD / 2048;       // 8192

    // s0: conv_Win (+ctr zero, +out zero) -> router
    conv_win_kernel<<<w1blocks + zblocks, 256>>>(Win, out, out_size, w1blocks);
    router_kernel<<<TS / RTOK, 256>>>(x, rw, rb);
    cudaEventRecord(e1, 0);

    // s1: conv_Wout starts when g1 starts (after router), runs under g1
    cudaStreamWaitEvent(s1, e1, 0);
    conv_wout_kernel<<<w2blocks, 256, 0, s1>>>(Wout);
    cudaEventRecord(e2, s1);

    // s0: g1 (concurrent with conv_Wout), then g2 after both
    g1_kernel<<<dim3(TS / 128, FFD / 128, NE), 256, DSMEM>>>(bin);
    cudaStreamWaitEvent(0, e2, 0);
    g2_kernel<<<dim3(TS / 128, HD / 256, NE), 256, DSMEM>>>(bout, out, out_size);

    cudaEventDestroy(e1);
    cudaEventDestroy(e2);
    cudaStreamDestroy(s1);
}